// round 1
// baseline (speedup 1.0000x reference)
#include <cuda_runtime.h>
#include <cuda_bf16.h>
#include <cstdint>

// Volume rendering composite.
// Inputs (metadata order): depth [N,192,1] f32, rgb [N,192,3] f32, sigma [N,192,1] f32
// Output (concatenated, f32): color [N,3], depth_out [N,1], acc_map [N,1], weights [N,192,1]

#define NRAYS 65536
#define NSAMP 192
#define NCHUNK (NSAMP / 32)   // 6

__global__ void __launch_bounds__(256)
volrend_kernel(const float* __restrict__ depth,
               const float* __restrict__ rgb,
               const float* __restrict__ sigma,
               float* __restrict__ out)
{
    const int gwarp = (blockIdx.x * blockDim.x + threadIdx.x) >> 5;
    const int lane  = threadIdx.x & 31;
    if (gwarp >= NRAYS) return;
    const int ray = gwarp;

    const float* __restrict__ dptr = depth + (size_t)ray * NSAMP;
    const float* __restrict__ sptr = sigma + (size_t)ray * NSAMP;
    const float* __restrict__ rptr = rgb   + (size_t)ray * NSAMP * 3;

    float* __restrict__ color_out = out;                                  // [N,3]
    float* __restrict__ depth_out = out + (size_t)NRAYS * 3;              // [N]
    float* __restrict__ acc_out   = out + (size_t)NRAYS * 4;              // [N]
    float* __restrict__ w_out     = out + (size_t)NRAYS * 5
                                        + (size_t)ray * NSAMP;            // [192]

    const float BOARDER = 1e10f;
    const float EPS     = 1e-10f;
    const float LOG2E   = 1.4426950408889634f;

    float carry = 1.0f;                 // transmittance entering this chunk
    float c0 = 0.f, c1 = 0.f, c2 = 0.f, dacc = 0.f, aacc = 0.f;

    #pragma unroll
    for (int c = 0; c < NCHUNK; ++c) {
        const int s = c * 32 + lane;

        // coalesced primary loads
        const float dep = dptr[s];
        const float sg  = sptr[s];

        // delta_i = depth_{i+1} - depth_i ; last sample padded with BOARDER.
        float delta;
        if (s == NSAMP - 1) {
            delta = BOARDER;
        } else {
            delta = dptr[s + 1] - dep;   // neighbor load: L1 hit for 31/32 lanes
        }

        // alpha = 1 - exp(-relu(sigma)*delta); surv = exp(...) + eps
        const float x = fmaxf(sg, 0.0f) * delta;
        const float e = exp2f(-x * LOG2E);     // MUFU.EX2 path
        const float alpha = 1.0f - e;
        float surv = e + EPS;

        // inclusive warp-scan product of surv
        float incl = surv;
        #pragma unroll
        for (int off = 1; off < 32; off <<= 1) {
            const float v = __shfl_up_sync(0xffffffffu, incl, off);
            if (lane >= off) incl *= v;
        }
        // exclusive scan -> transmittance before this sample
        float excl = __shfl_up_sync(0xffffffffu, incl, 1);
        if (lane == 0) excl = 1.0f;
        const float T = carry * excl;
        const float w = alpha * T;

        // rgb: 3 floats per sample; warp covers 384 contiguous bytes -> full sectors
        const float r0 = rptr[3 * s + 0];
        const float r1 = rptr[3 * s + 1];
        const float r2 = rptr[3 * s + 2];
        c0 = fmaf(w, __frcp_rn(1.0f + exp2f(-r0 * LOG2E)), c0);
        c1 = fmaf(w, __frcp_rn(1.0f + exp2f(-r1 * LOG2E)), c1);
        c2 = fmaf(w, __frcp_rn(1.0f + exp2f(-r2 * LOG2E)), c2);
        dacc = fmaf(w, dep, dacc);
        aacc += w;

        w_out[s] = w;   // coalesced store

        // propagate carry across chunks
        carry *= __shfl_sync(0xffffffffu, incl, 31);
    }

    // warp reduction of the 5 accumulators
    #pragma unroll
    for (int off = 16; off > 0; off >>= 1) {
        c0   += __shfl_down_sync(0xffffffffu, c0,   off);
        c1   += __shfl_down_sync(0xffffffffu, c1,   off);
        c2   += __shfl_down_sync(0xffffffffu, c2,   off);
        dacc += __shfl_down_sync(0xffffffffu, dacc, off);
        aacc += __shfl_down_sync(0xffffffffu, aacc, off);
    }
    if (lane == 0) {
        color_out[3 * ray + 0] = c0;
        color_out[3 * ray + 1] = c1;
        color_out[3 * ray + 2] = c2;
        depth_out[ray] = dacc;
        acc_out[ray]   = aacc;
    }
}

extern "C" void kernel_launch(void* const* d_in, const int* in_sizes, int n_in,
                              void* d_out, int out_size)
{
    const float* depth = (const float*)d_in[0];
    const float* rgb   = (const float*)d_in[1];
    const float* sigma = (const float*)d_in[2];
    float* out = (float*)d_out;

    // one warp per ray
    const int threads = 256;                       // 8 warps/block
    const int blocks  = NRAYS / (threads / 32);    // 8192
    volrend_kernel<<<blocks, threads>>>(depth, rgb, sigma, out);
}

// round 2
// speedup vs baseline: 1.0123x; 1.0123x over previous
#include <cuda_runtime.h>
#include <cuda_bf16.h>
#include <cstdint>

// Volume rendering composite.
// Inputs (metadata order): depth [N,192,1] f32, rgb [N,192,3] f32, sigma [N,192,1] f32
// Output (concatenated, f32): color [N,3], depth_out [N,1], acc_map [N,1], weights [N,192,1]

#define NRAYS 65536
#define NSAMP 192
#define NCHUNK (NSAMP / 32)   // 6

__global__ void __launch_bounds__(256)
volrend_kernel(const float* __restrict__ depth,
               const float* __restrict__ rgb,
               const float* __restrict__ sigma,
               float* __restrict__ out)
{
    const int gwarp = (blockIdx.x * blockDim.x + threadIdx.x) >> 5;
    const int lane  = threadIdx.x & 31;
    if (gwarp >= NRAYS) return;
    const int ray = gwarp;

    const float* __restrict__ dptr = depth + (size_t)ray * NSAMP;
    const float* __restrict__ sptr = sigma + (size_t)ray * NSAMP;
    const float* __restrict__ rptr = rgb   + (size_t)ray * NSAMP * 3;

    float* __restrict__ color_out = out;                                  // [N,3]
    float* __restrict__ depth_out = out + (size_t)NRAYS * 3;              // [N]
    float* __restrict__ acc_out   = out + (size_t)NRAYS * 4;              // [N]
    float* __restrict__ w_out     = out + (size_t)NRAYS * 5
                                        + (size_t)ray * NSAMP;            // [192]

    const float BOARDER = 1e10f;
    const float EPS     = 1e-10f;
    const float LOG2E   = 1.4426950408889634f;

    float carry = 1.0f;                 // transmittance entering this chunk
    float c0 = 0.f, c1 = 0.f, c2 = 0.f, dacc = 0.f, aacc = 0.f;

    #pragma unroll
    for (int c = 0; c < NCHUNK; ++c) {
        const int s = c * 32 + lane;

        // coalesced primary loads
        const float dep = dptr[s];
        const float sg  = sptr[s];

        // delta_i = depth_{i+1} - depth_i ; last sample padded with BOARDER.
        float delta;
        if (s == NSAMP - 1) {
            delta = BOARDER;
        } else {
            delta = dptr[s + 1] - dep;   // neighbor load: L1 hit for 31/32 lanes
        }

        // alpha = 1 - exp(-relu(sigma)*delta); surv = exp(...) + eps
        const float x = fmaxf(sg, 0.0f) * delta;
        const float e = exp2f(-x * LOG2E);     // MUFU.EX2 path
        const float alpha = 1.0f - e;
        float surv = e + EPS;

        // inclusive warp-scan product of surv
        float incl = surv;
        #pragma unroll
        for (int off = 1; off < 32; off <<= 1) {
            const float v = __shfl_up_sync(0xffffffffu, incl, off);
            if (lane >= off) incl *= v;
        }
        // exclusive scan -> transmittance before this sample
        float excl = __shfl_up_sync(0xffffffffu, incl, 1);
        if (lane == 0) excl = 1.0f;
        const float T = carry * excl;
        const float w = alpha * T;

        // rgb: 3 floats per sample; warp covers 384 contiguous bytes -> full sectors
        const float r0 = rptr[3 * s + 0];
        const float r1 = rptr[3 * s + 1];
        const float r2 = rptr[3 * s + 2];
        c0 = fmaf(w, __frcp_rn(1.0f + exp2f(-r0 * LOG2E)), c0);
        c1 = fmaf(w, __frcp_rn(1.0f + exp2f(-r1 * LOG2E)), c1);
        c2 = fmaf(w, __frcp_rn(1.0f + exp2f(-r2 * LOG2E)), c2);
        dacc = fmaf(w, dep, dacc);
        aacc += w;

        w_out[s] = w;   // coalesced store

        // propagate carry across chunks
        carry *= __shfl_sync(0xffffffffu, incl, 31);
    }

    // warp reduction of the 5 accumulators
    #pragma unroll
    for (int off = 16; off > 0; off >>= 1) {
        c0   += __shfl_down_sync(0xffffffffu, c0,   off);
        c1   += __shfl_down_sync(0xffffffffu, c1,   off);
        c2   += __shfl_down_sync(0xffffffffu, c2,   off);
        dacc += __shfl_down_sync(0xffffffffu, dacc, off);
        aacc += __shfl_down_sync(0xffffffffu, aacc, off);
    }
    if (lane == 0) {
        color_out[3 * ray + 0] = c0;
        color_out[3 * ray + 1] = c1;
        color_out[3 * ray + 2] = c2;
        depth_out[ray] = dacc;
        acc_out[ray]   = aacc;
    }
}

extern "C" void kernel_launch(void* const* d_in, const int* in_sizes, int n_in,
                              void* d_out, int out_size)
{
    const float* depth = (const float*)d_in[0];
    const float* rgb   = (const float*)d_in[1];
    const float* sigma = (const float*)d_in[2];
    float* out = (float*)d_out;

    // one warp per ray
    const int threads = 256;                       // 8 warps/block
    const int blocks  = NRAYS / (threads / 32);    // 8192
    volrend_kernel<<<blocks, threads>>>(depth, rgb, sigma, out);
}

// round 3
// speedup vs baseline: 1.3491x; 1.3327x over previous
#include <cuda_runtime.h>
#include <cuda_bf16.h>
#include <cstdint>

// Volume rendering composite.
// Inputs: depth [N,192,1] f32, rgb [N,192,3] f32, sigma [N,192,1] f32
// Output (concat, f32): color [N,3], depth_out [N,1], acc_map [N,1], weights [N,192,1]
//
// One warp per ray. Lane l owns the 6 CONSECUTIVE samples [6l, 6l+6):
//  - depth/sigma: 3x LDG.64 per lane (fully coalesced, vectorized)
//  - rgb: 9x LDG.64 per lane (18 floats, contiguous)
//  - single warp-level scan for the whole ray:
//    local product of 6 survivals -> 5-step shuffle scan -> local prefix.

#define NRAYS 65536
#define NSAMP 192

__global__ void __launch_bounds__(256)
volrend_kernel(const float* __restrict__ depth,
               const float* __restrict__ rgb,
               const float* __restrict__ sigma,
               float* __restrict__ out)
{
    const int gwarp = (blockIdx.x * blockDim.x + threadIdx.x) >> 5;
    const int lane  = threadIdx.x & 31;
    const int ray   = gwarp;

    const float* __restrict__ dptr = depth + (size_t)ray * NSAMP + 6 * lane;
    const float* __restrict__ sptr = sigma + (size_t)ray * NSAMP + 6 * lane;
    const float* __restrict__ rptr = rgb   + (size_t)ray * NSAMP * 3 + 18 * lane;

    const float BOARDER = 1e10f;
    const float EPS     = 1e-10f;
    const float LOG2E   = 1.4426950408889634f;

    // ---- front-batched loads (max MLP; all independent) ----
    float2 d01 = *(const float2*)(dptr + 0);
    float2 d23 = *(const float2*)(dptr + 2);
    float2 d45 = *(const float2*)(dptr + 4);
    float2 g01 = *(const float2*)(sptr + 0);
    float2 g23 = *(const float2*)(sptr + 2);
    float2 g45 = *(const float2*)(sptr + 4);

    float rf[18];
    #pragma unroll
    for (int i = 0; i < 9; ++i) {
        const float2 t = ((const float2*)rptr)[i];
        rf[2 * i]     = t.x;
        rf[2 * i + 1] = t.y;
    }

    float d[6] = { d01.x, d01.y, d23.x, d23.y, d45.x, d45.y };
    float g[6] = { g01.x, g01.y, g23.x, g23.y, g45.x, g45.y };

    // ---- deltas (neighbor's first depth via one shuffle) ----
    const float dnext = __shfl_down_sync(0xffffffffu, d[0], 1);
    float delta[6];
    #pragma unroll
    for (int j = 0; j < 5; ++j) delta[j] = d[j + 1] - d[j];
    delta[5] = (lane == 31) ? BOARDER : (dnext - d[5]);

    // ---- survival probs & alphas ----
    float surv[6], alpha[6];
    #pragma unroll
    for (int j = 0; j < 6; ++j) {
        const float x = fmaxf(g[j], 0.0f) * delta[j];
        const float e = exp2f(-x * LOG2E);   // MUFU.EX2
        alpha[j] = 1.0f - e;
        surv[j]  = e + EPS;
    }

    // ---- local exclusive prefix products ----
    float P[6];
    P[0] = 1.0f;
    #pragma unroll
    for (int j = 1; j < 6; ++j) P[j] = P[j - 1] * surv[j - 1];
    const float ploc = P[5] * surv[5];

    // ---- single warp-level scan over per-lane products ----
    float incl = ploc;
    #pragma unroll
    for (int off = 1; off < 32; off <<= 1) {
        const float v = __shfl_up_sync(0xffffffffu, incl, off);
        if (lane >= off) incl *= v;
    }
    float excl = __shfl_up_sync(0xffffffffu, incl, 1);
    if (lane == 0) excl = 1.0f;

    // ---- weights ----
    float w[6];
    #pragma unroll
    for (int j = 0; j < 6; ++j) w[j] = alpha[j] * (excl * P[j]);

    // ---- store weights (3x STG.64, coalesced) ----
    float* __restrict__ w_out = out + (size_t)NRAYS * 5
                                    + (size_t)ray * NSAMP + 6 * lane;
    *(float2*)(w_out + 0) = make_float2(w[0], w[1]);
    *(float2*)(w_out + 2) = make_float2(w[2], w[3]);
    *(float2*)(w_out + 4) = make_float2(w[4], w[5]);

    // ---- accumulate color / depth / acc ----
    float c0 = 0.f, c1 = 0.f, c2 = 0.f, dacc = 0.f, aacc = 0.f;
    #pragma unroll
    for (int j = 0; j < 6; ++j) {
        const float s0 = __frcp_rn(1.0f + exp2f(-rf[3 * j + 0] * LOG2E));
        const float s1 = __frcp_rn(1.0f + exp2f(-rf[3 * j + 1] * LOG2E));
        const float s2 = __frcp_rn(1.0f + exp2f(-rf[3 * j + 2] * LOG2E));
        c0   = fmaf(w[j], s0, c0);
        c1   = fmaf(w[j], s1, c1);
        c2   = fmaf(w[j], s2, c2);
        dacc = fmaf(w[j], d[j], dacc);
        aacc += w[j];
    }

    // ---- warp reduction ----
    #pragma unroll
    for (int off = 16; off > 0; off >>= 1) {
        c0   += __shfl_down_sync(0xffffffffu, c0,   off);
        c1   += __shfl_down_sync(0xffffffffu, c1,   off);
        c2   += __shfl_down_sync(0xffffffffu, c2,   off);
        dacc += __shfl_down_sync(0xffffffffu, dacc, off);
        aacc += __shfl_down_sync(0xffffffffu, aacc, off);
    }
    if (lane == 0) {
        out[3 * ray + 0] = c0;
        out[3 * ray + 1] = c1;
        out[3 * ray + 2] = c2;
        out[(size_t)NRAYS * 3 + ray] = dacc;
        out[(size_t)NRAYS * 4 + ray] = aacc;
    }
}

extern "C" void kernel_launch(void* const* d_in, const int* in_sizes, int n_in,
                              void* d_out, int out_size)
{
    const float* depth = (const float*)d_in[0];
    const float* rgb   = (const float*)d_in[1];
    const float* sigma = (const float*)d_in[2];
    float* out = (float*)d_out;

    const int threads = 256;                    // 8 warps/block
    const int blocks  = NRAYS / (threads / 32); // 8192
    volrend_kernel<<<blocks, threads>>>(depth, rgb, sigma, out);
}

// round 4
// speedup vs baseline: 1.4103x; 1.0454x over previous
#include <cuda_runtime.h>
#include <cuda_bf16.h>
#include <cstdint>

// Volume rendering composite.
// Inputs: depth [N,192,1] f32, rgb [N,192,3] f32, sigma [N,192,1] f32
// Output (concat, f32): color [N,3], depth_out [N,1], acc_map [N,1], weights [N,192,1]
//
// One warp per ray; lane l owns the 6 consecutive samples [6l, 6l+6).
// All math on approx MUFU paths (ex2.approx / rcp.approx); sigmoids computed
// eagerly so MUFU latency overlaps the warp-scan dependency chain.

#define NRAYS 65536
#define NSAMP 192

__device__ __forceinline__ float ex2_approx(float x) {
    float r;
    asm("ex2.approx.f32 %0, %1;" : "=f"(r) : "f"(x));
    return r;
}
__device__ __forceinline__ float rcp_approx(float x) {
    float r;
    asm("rcp.approx.f32 %0, %1;" : "=f"(r) : "f"(x));
    return r;
}
__device__ __forceinline__ float sigmoid_fast(float x) {
    // 1 / (1 + 2^(-x*log2e))
    const float LOG2E = 1.4426950408889634f;
    return rcp_approx(1.0f + ex2_approx(-x * LOG2E));
}

__global__ void __launch_bounds__(256, 6)
volrend_kernel(const float* __restrict__ depth,
               const float* __restrict__ rgb,
               const float* __restrict__ sigma,
               float* __restrict__ out)
{
    const int gwarp = (blockIdx.x * blockDim.x + threadIdx.x) >> 5;
    const int lane  = threadIdx.x & 31;
    const int ray   = gwarp;

    const float* __restrict__ dptr = depth + (size_t)ray * NSAMP + 6 * lane;
    const float* __restrict__ sptr = sigma + (size_t)ray * NSAMP + 6 * lane;
    const float* __restrict__ rptr = rgb   + (size_t)ray * NSAMP * 3 + 18 * lane;

    const float BOARDER = 1e10f;
    const float EPS     = 1e-10f;
    const float LOG2E   = 1.4426950408889634f;

    // ---- front-batched streaming loads (no reuse anywhere -> .cs) ----
    const float2 d01 = __ldcs((const float2*)(dptr + 0));
    const float2 d23 = __ldcs((const float2*)(dptr + 2));
    const float2 d45 = __ldcs((const float2*)(dptr + 4));
    const float2 g01 = __ldcs((const float2*)(sptr + 0));
    const float2 g23 = __ldcs((const float2*)(sptr + 2));
    const float2 g45 = __ldcs((const float2*)(sptr + 4));

    float s[18];   // sigmoid(rgb) computed eagerly (independent of the scan)
    #pragma unroll
    for (int i = 0; i < 9; ++i) {
        const float2 t = __ldcs((const float2*)rptr + i);
        s[2 * i]     = t.x;
        s[2 * i + 1] = t.y;
    }
    #pragma unroll
    for (int i = 0; i < 18; ++i) s[i] = sigmoid_fast(s[i]);

    float d[6] = { d01.x, d01.y, d23.x, d23.y, d45.x, d45.y };
    float g[6] = { g01.x, g01.y, g23.x, g23.y, g45.x, g45.y };

    // ---- deltas (neighbor's first depth via one shuffle) ----
    const float dnext = __shfl_down_sync(0xffffffffu, d[0], 1);
    float delta5 = (lane == 31) ? BOARDER : (dnext - d[5]);

    // ---- survival probs (alpha recomputed later as 1 - surv + EPS) ----
    float surv[6];
    #pragma unroll
    for (int j = 0; j < 6; ++j) {
        const float dl = (j < 5) ? (d[j + 1] - d[j]) : delta5;
        const float x  = fmaxf(g[j], 0.0f) * dl;
        surv[j] = ex2_approx(-x * LOG2E) + EPS;
    }

    // ---- local exclusive prefix products ----
    float P[6];
    P[0] = 1.0f;
    #pragma unroll
    for (int j = 1; j < 6; ++j) P[j] = P[j - 1] * surv[j - 1];
    const float ploc = P[5] * surv[5];

    // ---- single 5-step warp scan over per-lane products ----
    float incl = ploc;
    #pragma unroll
    for (int off = 1; off < 32; off <<= 1) {
        const float v = __shfl_up_sync(0xffffffffu, incl, off);
        if (lane >= off) incl *= v;
    }
    float excl = __shfl_up_sync(0xffffffffu, incl, 1);
    if (lane == 0) excl = 1.0f;

    // ---- weights: w = alpha * T,  alpha = 1 - surv + EPS ----
    float w[6];
    #pragma unroll
    for (int j = 0; j < 6; ++j)
        w[j] = (1.0f - surv[j] + EPS) * (excl * P[j]);

    // ---- store weights (streaming, coalesced) ----
    float* __restrict__ w_out = out + (size_t)NRAYS * 5
                                    + (size_t)ray * NSAMP + 6 * lane;
    __stcs((float2*)(w_out + 0), make_float2(w[0], w[1]));
    __stcs((float2*)(w_out + 2), make_float2(w[2], w[3]));
    __stcs((float2*)(w_out + 4), make_float2(w[4], w[5]));

    // ---- accumulate color / depth / acc ----
    float c0 = 0.f, c1 = 0.f, c2 = 0.f, dacc = 0.f, aacc = 0.f;
    #pragma unroll
    for (int j = 0; j < 6; ++j) {
        c0   = fmaf(w[j], s[3 * j + 0], c0);
        c1   = fmaf(w[j], s[3 * j + 1], c1);
        c2   = fmaf(w[j], s[3 * j + 2], c2);
        dacc = fmaf(w[j], d[j], dacc);
        aacc += w[j];
    }

    // ---- warp reduction ----
    #pragma unroll
    for (int off = 16; off > 0; off >>= 1) {
        c0   += __shfl_down_sync(0xffffffffu, c0,   off);
        c1   += __shfl_down_sync(0xffffffffu, c1,   off);
        c2   += __shfl_down_sync(0xffffffffu, c2,   off);
        dacc += __shfl_down_sync(0xffffffffu, dacc, off);
        aacc += __shfl_down_sync(0xffffffffu, aacc, off);
    }
    if (lane == 0) {
        out[3 * ray + 0] = c0;
        out[3 * ray + 1] = c1;
        out[3 * ray + 2] = c2;
        out[(size_t)NRAYS * 3 + ray] = dacc;
        out[(size_t)NRAYS * 4 + ray] = aacc;
    }
}

extern "C" void kernel_launch(void* const* d_in, const int* in_sizes, int n_in,
                              void* d_out, int out_size)
{
    const float* depth = (const float*)d_in[0];
    const float* rgb   = (const float*)d_in[1];
    const float* sigma = (const float*)d_in[2];
    float* out = (float*)d_out;

    const int threads = 256;                    // 8 warps/block
    const int blocks  = NRAYS / (threads / 32); // 8192
    volrend_kernel<<<blocks, threads>>>(depth, rgb, sigma, out);
}